// round 3
// baseline (speedup 1.0000x reference)
#include <cuda_runtime.h>
#include <cstdint>

#define D 128
#define BM 64   // rows per block in GEMM
#define N_MAX 100000

// Scratch buffers as float4 arrays -> guaranteed 16B alignment for wide ld/st.
__device__ float4 g_h4[N_MAX * (D / 4)];   // h = x @ W^T + b
__device__ float4 g_wt4[D * D / 4];        // W^T

// ---------------------------------------------------------------------------
// Kernel 0: transpose W (tiny)
// ---------------------------------------------------------------------------
__global__ void transpose_w_kernel(const float* __restrict__ W) {
    int idx = blockIdx.x * blockDim.x + threadIdx.x;   // 0 .. 16383
    int j = idx >> 7;          // row of W
    int k = idx & (D - 1);     // col of W
    float* wt = (float*)g_wt4;
    wt[k * D + j] = W[j * D + k];
}

// ---------------------------------------------------------------------------
// Kernel 1: h = x @ W^T + b
// 256 threads, 64 rows x 128 cols per block. W^T resident in smem (64KB),
// x tile (64x128, 32KB) in smem. 8x4 accumulators per thread.
// ---------------------------------------------------------------------------
__global__ __launch_bounds__(256, 2)
void gemm_kernel(const float* __restrict__ x, const float* __restrict__ bias,
                 int n_rows) {
    extern __shared__ float4 smem4[];
    float4* Ws4 = smem4;                 // [128][32] f4 : row k holds W^T[k][:]
    float4* Xs4 = smem4 + D * (D / 4);   // [64][32]  f4

    const int tid  = threadIdx.x;
    const int row0 = blockIdx.x * BM;
    const int rows = min(BM, n_rows - row0);

    #pragma unroll
    for (int i = 0; i < (D * D / 4) / 256; i++)  // 16 iters
        Ws4[tid + i * 256] = g_wt4[tid + i * 256];

    {
        const float4* x4 = (const float4*)(x + (long long)row0 * D);
        const int nf4 = rows * (D / 4);
        for (int i = tid; i < nf4; i += 256)
            Xs4[i] = x4[i];
    }
    __syncthreads();

    const int warp = tid >> 5;
    const int lane = tid & 31;
    const int r0 = warp * 8;

    float acc[8][4];
    #pragma unroll
    for (int i = 0; i < 8; i++)
        #pragma unroll
        for (int j = 0; j < 4; j++) acc[i][j] = 0.0f;

    #pragma unroll 4
    for (int k = 0; k < D; k += 4) {
        float4 wv0 = Ws4[(k + 0) * 32 + lane];
        float4 wv1 = Ws4[(k + 1) * 32 + lane];
        float4 wv2 = Ws4[(k + 2) * 32 + lane];
        float4 wv3 = Ws4[(k + 3) * 32 + lane];
        #pragma unroll
        for (int i = 0; i < 8; i++) {
            float4 xv = Xs4[(r0 + i) * 32 + (k >> 2)];  // broadcast within warp
            acc[i][0] += xv.x * wv0.x; acc[i][1] += xv.x * wv0.y;
            acc[i][2] += xv.x * wv0.z; acc[i][3] += xv.x * wv0.w;
            acc[i][0] += xv.y * wv1.x; acc[i][1] += xv.y * wv1.y;
            acc[i][2] += xv.y * wv1.z; acc[i][3] += xv.y * wv1.w;
            acc[i][0] += xv.z * wv2.x; acc[i][1] += xv.z * wv2.y;
            acc[i][2] += xv.z * wv2.z; acc[i][3] += xv.z * wv2.w;
            acc[i][0] += xv.w * wv3.x; acc[i][1] += xv.w * wv3.y;
            acc[i][2] += xv.w * wv3.z; acc[i][3] += xv.w * wv3.w;
        }
    }

    float4 bv = ((const float4*)bias)[lane];
    #pragma unroll
    for (int i = 0; i < 8; i++) {
        int r = r0 + i;
        if (r < rows) {
            float4 o;
            o.x = acc[i][0] + bv.x;
            o.y = acc[i][1] + bv.y;
            o.z = acc[i][2] + bv.z;
            o.w = acc[i][3] + bv.w;
            g_h4[(long long)(row0 + r) * 32 + lane] = o;
        }
    }
}

// ---------------------------------------------------------------------------
// Kernel 2: edge scatter. One warp per edge (int32 indices!).
// Lane gathers a float4 of h[src], scales by w, vector-reduces into out[dst].
// ---------------------------------------------------------------------------
__global__ __launch_bounds__(256)
void scatter_kernel(const int* __restrict__ src,
                    const int* __restrict__ dst,
                    const float* __restrict__ w,
                    float* __restrict__ out,
                    int n_edges, int n_nodes) {
    long long gtid = (long long)blockIdx.x * blockDim.x + threadIdx.x;
    int e = (int)(gtid >> 5);
    int lane = threadIdx.x & 31;
    if (e >= n_edges) return;

    int s = src[e];
    int d = dst[e];
    // Safety guard: if index dtype assumption is wrong, skip instead of IMA
    if ((unsigned)s >= (unsigned)n_nodes || (unsigned)d >= (unsigned)n_nodes)
        return;
    float wv = w[e];

    float4 v = g_h4[(long long)s * 32 + lane];
    v.x *= wv; v.y *= wv; v.z *= wv; v.w *= wv;

    float* p = out + (long long)d * D + lane * 4;   // 16B aligned
    asm volatile("red.global.add.v4.f32 [%0], {%1, %2, %3, %4};"
                 :: "l"(p), "f"(v.x), "f"(v.y), "f"(v.z), "f"(v.w)
                 : "memory");
}

// ---------------------------------------------------------------------------
extern "C" void kernel_launch(void* const* d_in, const int* in_sizes, int n_in,
                              void* d_out, int out_size) {
    const float* x   = (const float*)d_in[0];
    const float* w   = (const float*)d_in[1];
    const float* W   = (const float*)d_in[2];
    const float* b   = (const float*)d_in[3];
    const int*   src = (const int*)d_in[4];   // JAX x64-disabled: int64 -> int32
    const int*   dst = (const int*)d_in[5];

    int N = in_sizes[0] / D;
    int E = in_sizes[1];
    float* out = (float*)d_out;

    transpose_w_kernel<<<(D * D) / 256, 256>>>(W);

    const int smem_bytes = (D * D + BM * D) * sizeof(float);  // 96 KB
    cudaFuncSetAttribute(gemm_kernel,
                         cudaFuncAttributeMaxDynamicSharedMemorySize, smem_bytes);
    gemm_kernel<<<(N + BM - 1) / BM, 256, smem_bytes>>>(x, b, N);

    cudaMemsetAsync(d_out, 0, (size_t)out_size * sizeof(float), 0);

    long long total_threads = (long long)E * 32;
    int blocks = (int)((total_threads + 255) / 256);
    scatter_kernel<<<blocks, 256>>>(src, dst, w, out, E, N);
}

// round 4
// speedup vs baseline: 2.1450x; 2.1450x over previous
#include <cuda_runtime.h>
#include <cstdint>

#define D 128
#define BM 64
#define N_MAX 100000
#define E_MAX 3200000

// Scratch (16B-aligned where wide-accessed)
__device__ float4 g_h4[N_MAX * (D / 4)];   // h = x @ W^T + b
__device__ float4 g_wt4[D * D / 4];        // W^T
__device__ int    g_cnt[N_MAX];            // histogram -> cursor
__device__ int    g_base[N_MAX];           // segment start per node
__device__ int    g_total;                 // bump allocator
__device__ int    g_esrc[E_MAX];           // grouped: src per slot
__device__ float  g_ew[E_MAX];             // grouped: weight per slot

// ---------------------------------------------------------------------------
// zero counters
// ---------------------------------------------------------------------------
__global__ void zero_kernel(int n_nodes) {
    int i = blockIdx.x * blockDim.x + threadIdx.x;
    if (i < n_nodes) g_cnt[i] = 0;
    if (i == 0) g_total = 0;
}

// ---------------------------------------------------------------------------
// transpose W (tiny)
// ---------------------------------------------------------------------------
__global__ void transpose_w_kernel(const float* __restrict__ W) {
    int idx = blockIdx.x * blockDim.x + threadIdx.x;
    int j = idx >> 7;
    int k = idx & (D - 1);
    ((float*)g_wt4)[k * D + j] = W[j * D + k];
}

// ---------------------------------------------------------------------------
// histogram of dst
// ---------------------------------------------------------------------------
__global__ void hist_kernel(const int* __restrict__ dst, int n_edges) {
    int e = blockIdx.x * blockDim.x + threadIdx.x;
    if (e < n_edges) atomicAdd(&g_cnt[dst[e]], 1);
}

// ---------------------------------------------------------------------------
// segment base assignment: in-block exclusive scan + one global bump per block.
// Segments need not be in node order — just disjoint & contiguous per node.
// Writes g_base[i]; resets g_cnt[i] to base (cursor for placement).
// ---------------------------------------------------------------------------
__global__ void assign_base_kernel(int n_nodes) {
    __shared__ int warp_tot[8];
    __shared__ int block_base;
    int i = blockIdx.x * 256 + threadIdx.x;
    int lane = threadIdx.x & 31;
    int warp = threadIdx.x >> 5;

    int c = (i < n_nodes) ? g_cnt[i] : 0;
    // inclusive warp scan
    int v = c;
    #pragma unroll
    for (int off = 1; off < 32; off <<= 1) {
        int t = __shfl_up_sync(0xffffffffu, v, off);
        if (lane >= off) v += t;
    }
    if (lane == 31) warp_tot[warp] = v;
    __syncthreads();
    if (warp == 0) {
        int wv = (lane < 8) ? warp_tot[lane] : 0;
        #pragma unroll
        for (int off = 1; off < 8; off <<= 1) {
            int t = __shfl_up_sync(0xffffffffu, wv, off);
            if (lane >= off) wv += t;
        }
        if (lane < 8) warp_tot[lane] = wv;   // inclusive warp totals
        if (lane == 7) block_base = atomicAdd(&g_total, wv);
    }
    __syncthreads();
    int excl = v - c + (warp > 0 ? warp_tot[warp - 1] : 0);
    if (i < n_nodes) {
        int base = block_base + excl;
        g_base[i] = base;
        g_cnt[i]  = base;   // becomes cursor
    }
}

// ---------------------------------------------------------------------------
// placement: group (src, w) by dst
// ---------------------------------------------------------------------------
__global__ void place_kernel(const int* __restrict__ src,
                             const int* __restrict__ dst,
                             const float* __restrict__ w,
                             int n_edges) {
    int e = blockIdx.x * blockDim.x + threadIdx.x;
    if (e >= n_edges) return;
    int d = dst[e];
    int pos = atomicAdd(&g_cnt[d], 1);
    g_esrc[pos] = src[e];
    g_ew[pos]   = w[e];
}

// ---------------------------------------------------------------------------
// GEMM: h = x @ W^T + b  (unchanged from passing version)
// ---------------------------------------------------------------------------
__global__ __launch_bounds__(256, 2)
void gemm_kernel(const float* __restrict__ x, const float* __restrict__ bias,
                 int n_rows) {
    extern __shared__ float4 smem4[];
    float4* Ws4 = smem4;                 // [128][32] f4
    float4* Xs4 = smem4 + D * (D / 4);   // [64][32]  f4

    const int tid  = threadIdx.x;
    const int row0 = blockIdx.x * BM;
    const int rows = min(BM, n_rows - row0);

    #pragma unroll
    for (int i = 0; i < (D * D / 4) / 256; i++)
        Ws4[tid + i * 256] = g_wt4[tid + i * 256];
    {
        const float4* x4 = (const float4*)(x + (long long)row0 * D);
        const int nf4 = rows * (D / 4);
        for (int i = tid; i < nf4; i += 256)
            Xs4[i] = x4[i];
    }
    __syncthreads();

    const int warp = tid >> 5;
    const int lane = tid & 31;
    const int r0 = warp * 8;

    float acc[8][4];
    #pragma unroll
    for (int i = 0; i < 8; i++)
        #pragma unroll
        for (int j = 0; j < 4; j++) acc[i][j] = 0.0f;

    #pragma unroll 4
    for (int k = 0; k < D; k += 4) {
        float4 wv0 = Ws4[(k + 0) * 32 + lane];
        float4 wv1 = Ws4[(k + 1) * 32 + lane];
        float4 wv2 = Ws4[(k + 2) * 32 + lane];
        float4 wv3 = Ws4[(k + 3) * 32 + lane];
        #pragma unroll
        for (int i = 0; i < 8; i++) {
            float4 xv = Xs4[(r0 + i) * 32 + (k >> 2)];
            acc[i][0] += xv.x * wv0.x; acc[i][1] += xv.x * wv0.y;
            acc[i][2] += xv.x * wv0.z; acc[i][3] += xv.x * wv0.w;
            acc[i][0] += xv.y * wv1.x; acc[i][1] += xv.y * wv1.y;
            acc[i][2] += xv.y * wv1.z; acc[i][3] += xv.y * wv1.w;
            acc[i][0] += xv.z * wv2.x; acc[i][1] += xv.z * wv2.y;
            acc[i][2] += xv.z * wv2.z; acc[i][3] += xv.z * wv2.w;
            acc[i][0] += xv.w * wv3.x; acc[i][1] += xv.w * wv3.y;
            acc[i][2] += xv.w * wv3.z; acc[i][3] += xv.w * wv3.w;
        }
    }

    float4 bv = ((const float4*)bias)[lane];
    #pragma unroll
    for (int i = 0; i < 8; i++) {
        int r = r0 + i;
        if (r < rows) {
            float4 o;
            o.x = acc[i][0] + bv.x;
            o.y = acc[i][1] + bv.y;
            o.z = acc[i][2] + bv.z;
            o.w = acc[i][3] + bv.w;
            g_h4[(long long)(row0 + r) * 32 + lane] = o;
        }
    }
}

// ---------------------------------------------------------------------------
// aggregate: one warp per node. Lane owns one float4 column (D/4 = 32 = warp).
// Register accumulation over the node's edge segment; single 512B store.
// No atomics, no output memset needed.
// ---------------------------------------------------------------------------
__global__ __launch_bounds__(256)
void aggregate_kernel(float* __restrict__ out, int n_nodes) {
    int node = (blockIdx.x * 256 + threadIdx.x) >> 5;
    int lane = threadIdx.x & 31;
    if (node >= n_nodes) return;

    int beg = g_base[node];
    int end = g_cnt[node];   // cursor ended at segment end

    float4 acc = make_float4(0.f, 0.f, 0.f, 0.f);

    // 2-way unrolled for MLP
    int i = beg;
    for (; i + 2 <= end; i += 2) {
        int   s0 = g_esrc[i],     s1 = g_esrc[i + 1];
        float w0 = g_ew[i],       w1 = g_ew[i + 1];
        float4 v0 = g_h4[(long long)s0 * 32 + lane];
        float4 v1 = g_h4[(long long)s1 * 32 + lane];
        acc.x += v0.x * w0; acc.y += v0.y * w0;
        acc.z += v0.z * w0; acc.w += v0.w * w0;
        acc.x += v1.x * w1; acc.y += v1.y * w1;
        acc.z += v1.z * w1; acc.w += v1.w * w1;
    }
    if (i < end) {
        int s = g_esrc[i];
        float wv = g_ew[i];
        float4 v = g_h4[(long long)s * 32 + lane];
        acc.x += v.x * wv; acc.y += v.y * wv;
        acc.z += v.z * wv; acc.w += v.w * wv;
    }

    ((float4*)out)[(long long)node * 32 + lane] = acc;
}

// ---------------------------------------------------------------------------
extern "C" void kernel_launch(void* const* d_in, const int* in_sizes, int n_in,
                              void* d_out, int out_size) {
    const float* x   = (const float*)d_in[0];
    const float* w   = (const float*)d_in[1];
    const float* W   = (const float*)d_in[2];
    const float* b   = (const float*)d_in[3];
    const int*   src = (const int*)d_in[4];   // int32 (JAX x64 disabled)
    const int*   dst = (const int*)d_in[5];

    int N = in_sizes[0] / D;
    int E = in_sizes[1];
    float* out = (float*)d_out;

    int nb_nodes = (N + 255) / 256;
    int nb_edges = (E + 255) / 256;

    zero_kernel<<<nb_nodes, 256>>>(N);
    transpose_w_kernel<<<(D * D) / 256, 256>>>(W);
    hist_kernel<<<nb_edges, 256>>>(dst, E);
    assign_base_kernel<<<nb_nodes, 256>>>(N);
    place_kernel<<<nb_edges, 256>>>(src, dst, w, E);

    const int smem_bytes = (D * D + BM * D) * sizeof(float);  // 96 KB
    cudaFuncSetAttribute(gemm_kernel,
                         cudaFuncAttributeMaxDynamicSharedMemorySize, smem_bytes);
    gemm_kernel<<<(N + BM - 1) / BM, 256, smem_bytes>>>(x, b, N);

    int nb_agg = (N * 32 + 255) / 256;   // one warp per node
    aggregate_kernel<<<nb_agg, 256>>>(out, N);
}

// round 5
// speedup vs baseline: 2.3138x; 1.0787x over previous
#include <cuda_runtime.h>
#include <cstdint>

#define D 128
#define BM 64
#define N_MAX 100000
#define E_MAX 3200000

// ---- packed f32x2 helpers (2x fp32 FMA throughput on sm_103a) -------------
#define FMA_F32X2(d, a, b, c) \
    asm("fma.rn.f32x2 %0, %1, %2, %3;" : "=l"(d) : "l"(a), "l"(b), "l"(c))
#define ADD_F32X2(d, a, b) \
    asm("add.rn.f32x2 %0, %1, %2;" : "=l"(d) : "l"(a), "l"(b))
#define PACK_DUP_F32X2(out, r) \
    asm("mov.b64 %0, {%1, %1};" : "=l"(out) : "r"(r))

// Scratch
__device__ float4 g_h4[N_MAX * (D / 4)];   // h = x @ W^T + b
__device__ float4 g_wt4[D * D / 4];        // W^T
__device__ int    g_cnt[N_MAX];            // histogram -> cursor -> seg end
__device__ int    g_base[N_MAX];           // segment start per node
__device__ int    g_total;                 // bump allocator
__device__ int2   g_edge[E_MAX];           // grouped (src, w-bits) per slot

// ---------------------------------------------------------------------------
__global__ void zero_kernel(int n_nodes) {
    int i = blockIdx.x * blockDim.x + threadIdx.x;
    if (i < n_nodes) g_cnt[i] = 0;
    if (i == 0) g_total = 0;
}

__global__ void transpose_w_kernel(const float* __restrict__ W) {
    int idx = blockIdx.x * blockDim.x + threadIdx.x;
    int j = idx >> 7;
    int k = idx & (D - 1);
    ((float*)g_wt4)[k * D + j] = W[j * D + k];
}

__global__ void hist_kernel(const int* __restrict__ dst, int n_edges) {
    int e = blockIdx.x * blockDim.x + threadIdx.x;
    if (e < n_edges) atomicAdd(&g_cnt[dst[e]], 1);
}

__global__ void assign_base_kernel(int n_nodes) {
    __shared__ int warp_tot[8];
    __shared__ int block_base;
    int i = blockIdx.x * 256 + threadIdx.x;
    int lane = threadIdx.x & 31;
    int warp = threadIdx.x >> 5;

    int c = (i < n_nodes) ? g_cnt[i] : 0;
    int v = c;
    #pragma unroll
    for (int off = 1; off < 32; off <<= 1) {
        int t = __shfl_up_sync(0xffffffffu, v, off);
        if (lane >= off) v += t;
    }
    if (lane == 31) warp_tot[warp] = v;
    __syncthreads();
    if (warp == 0) {
        int wv = (lane < 8) ? warp_tot[lane] : 0;
        #pragma unroll
        for (int off = 1; off < 8; off <<= 1) {
            int t = __shfl_up_sync(0xffffffffu, wv, off);
            if (lane >= off) wv += t;
        }
        if (lane < 8) warp_tot[lane] = wv;
        if (lane == 7) block_base = atomicAdd(&g_total, wv);
    }
    __syncthreads();
    int excl = v - c + (warp > 0 ? warp_tot[warp - 1] : 0);
    if (i < n_nodes) {
        int base = block_base + excl;
        g_base[i] = base;
        g_cnt[i]  = base;
    }
}

__global__ void place_kernel(const int* __restrict__ src,
                             const int* __restrict__ dst,
                             const float* __restrict__ w,
                             int n_edges) {
    int e = blockIdx.x * blockDim.x + threadIdx.x;
    if (e >= n_edges) return;
    int d = dst[e];
    int pos = atomicAdd(&g_cnt[d], 1);
    g_edge[pos] = make_int2(src[e], __float_as_int(w[e]));
}

// ---------------------------------------------------------------------------
// GEMM: h = x @ W^T + b with packed f32x2 FMA (2x fp32 pipe throughput).
// Same tiling as the passing R4 version; accumulators hold column pairs.
// ---------------------------------------------------------------------------
__global__ __launch_bounds__(256, 2)
void gemm_kernel(const float* __restrict__ x, const float* __restrict__ bias,
                 int n_rows) {
    extern __shared__ float4 smem4[];
    float4* Ws4 = smem4;                 // [128][32] f4: row k holds W^T[k][:]
    float4* Xs4 = smem4 + D * (D / 4);   // [64][32]  f4

    const int tid  = threadIdx.x;
    const int row0 = blockIdx.x * BM;
    const int rows = min(BM, n_rows - row0);

    #pragma unroll
    for (int i = 0; i < (D * D / 4) / 256; i++)
        Ws4[tid + i * 256] = g_wt4[tid + i * 256];
    {
        const float4* x4 = (const float4*)(x + (long long)row0 * D);
        const int nf4 = rows * (D / 4);
        for (int i = tid; i < nf4; i += 256)
            Xs4[i] = x4[i];
    }
    __syncthreads();

    const int warp = tid >> 5;
    const int lane = tid & 31;
    const int r0 = warp * 8;

    const ulonglong2* Ws2 = (const ulonglong2*)Ws4;  // same 16B slots, as f32x2 pairs

    unsigned long long acc[8][2];   // [row][colpair]: (c0,c1),(c2,c3) of cols 4*lane..
    #pragma unroll
    for (int i = 0; i < 8; i++) { acc[i][0] = 0ull; acc[i][1] = 0ull; }

    #pragma unroll 4
    for (int k = 0; k < D; k += 4) {
        ulonglong2 wv0 = Ws2[(k + 0) * 32 + lane];
        ulonglong2 wv1 = Ws2[(k + 1) * 32 + lane];
        ulonglong2 wv2 = Ws2[(k + 2) * 32 + lane];
        ulonglong2 wv3 = Ws2[(k + 3) * 32 + lane];
        #pragma unroll
        for (int i = 0; i < 8; i++) {
            float4 xv = Xs4[(r0 + i) * 32 + (k >> 2)];  // broadcast within warp
            unsigned long long xd;
            PACK_DUP_F32X2(xd, __float_as_uint(xv.x));
            FMA_F32X2(acc[i][0], xd, wv0.x, acc[i][0]);
            FMA_F32X2(acc[i][1], xd, wv0.y, acc[i][1]);
            PACK_DUP_F32X2(xd, __float_as_uint(xv.y));
            FMA_F32X2(acc[i][0], xd, wv1.x, acc[i][0]);
            FMA_F32X2(acc[i][1], xd, wv1.y, acc[i][1]);
            PACK_DUP_F32X2(xd, __float_as_uint(xv.z));
            FMA_F32X2(acc[i][0], xd, wv2.x, acc[i][0]);
            FMA_F32X2(acc[i][1], xd, wv2.y, acc[i][1]);
            PACK_DUP_F32X2(xd, __float_as_uint(xv.w));
            FMA_F32X2(acc[i][0], xd, wv3.x, acc[i][0]);
            FMA_F32X2(acc[i][1], xd, wv3.y, acc[i][1]);
        }
    }

    // bias add (packed) + store
    ulonglong2 bv = ((const ulonglong2*)bias)[lane];
    ulonglong2* out2 = (ulonglong2*)g_h4;
    #pragma unroll
    for (int i = 0; i < 8; i++) {
        int r = r0 + i;
        if (r < rows) {
            ulonglong2 o;
            ADD_F32X2(o.x, acc[i][0], bv.x);
            ADD_F32X2(o.y, acc[i][1], bv.y);
            out2[(long long)(row0 + r) * 32 + lane] = o;
        }
    }
}

// ---------------------------------------------------------------------------
// aggregate: one warp per node, lane owns one float4 column. Register
// accumulation over the node's segment; one packed int2 load per edge.
// ---------------------------------------------------------------------------
__global__ __launch_bounds__(256)
void aggregate_kernel(float* __restrict__ out, int n_nodes) {
    int node = (blockIdx.x * 256 + threadIdx.x) >> 5;
    int lane = threadIdx.x & 31;
    if (node >= n_nodes) return;

    int beg = g_base[node];
    int end = g_cnt[node];

    float4 acc = make_float4(0.f, 0.f, 0.f, 0.f);

    int i = beg;
    for (; i + 4 <= end; i += 4) {
        int2 e0 = g_edge[i],     e1 = g_edge[i + 1];
        int2 e2 = g_edge[i + 2], e3 = g_edge[i + 3];
        float4 v0 = g_h4[(long long)e0.x * 32 + lane];
        float4 v1 = g_h4[(long long)e1.x * 32 + lane];
        float4 v2 = g_h4[(long long)e2.x * 32 + lane];
        float4 v3 = g_h4[(long long)e3.x * 32 + lane];
        float w0 = __int_as_float(e0.y), w1 = __int_as_float(e1.y);
        float w2 = __int_as_float(e2.y), w3 = __int_as_float(e3.y);
        acc.x += v0.x * w0; acc.y += v0.y * w0; acc.z += v0.z * w0; acc.w += v0.w * w0;
        acc.x += v1.x * w1; acc.y += v1.y * w1; acc.z += v1.z * w1; acc.w += v1.w * w1;
        acc.x += v2.x * w2; acc.y += v2.y * w2; acc.z += v2.z * w2; acc.w += v2.w * w2;
        acc.x += v3.x * w3; acc.y += v3.y * w3; acc.z += v3.z * w3; acc.w += v3.w * w3;
    }
    for (; i < end; i++) {
        int2 e = g_edge[i];
        float wv = __int_as_float(e.y);
        float4 v = g_h4[(long long)e.x * 32 + lane];
        acc.x += v.x * wv; acc.y += v.y * wv; acc.z += v.z * wv; acc.w += v.w * wv;
    }

    ((float4*)out)[(long long)node * 32 + lane] = acc;
}

// ---------------------------------------------------------------------------
extern "C" void kernel_launch(void* const* d_in, const int* in_sizes, int n_in,
                              void* d_out, int out_size) {
    const float* x   = (const float*)d_in[0];
    const float* w   = (const float*)d_in[1];
    const float* W   = (const float*)d_in[2];
    const float* b   = (const float*)d_in[3];
    const int*   src = (const int*)d_in[4];   // int32 (JAX x64 disabled)
    const int*   dst = (const int*)d_in[5];

    int N = in_sizes[0] / D;
    int E = in_sizes[1];
    float* out = (float*)d_out;

    int nb_nodes = (N + 255) / 256;
    int nb_edges = (E + 255) / 256;

    // Fork stream: GEMM (x,W,b only) runs concurrently with the edge-sort
    // pipeline (src,dst,w only). Standard capture-fork via events.
    cudaStream_t s2;
    cudaStreamCreate(&s2);
    cudaEvent_t evFork, evJoin;
    cudaEventCreateWithFlags(&evFork, cudaEventDisableTiming);
    cudaEventCreateWithFlags(&evJoin, cudaEventDisableTiming);

    zero_kernel<<<nb_nodes, 256>>>(N);
    transpose_w_kernel<<<(D * D) / 256, 256>>>(W);

    cudaEventRecord(evFork, 0);
    cudaStreamWaitEvent(s2, evFork, 0);

    const int smem_bytes = (D * D + BM * D) * sizeof(float);  // 96 KB
    cudaFuncSetAttribute(gemm_kernel,
                         cudaFuncAttributeMaxDynamicSharedMemorySize, smem_bytes);
    gemm_kernel<<<(N + BM - 1) / BM, 256, smem_bytes, s2>>>(x, b, N);
    cudaEventRecord(evJoin, s2);

    hist_kernel<<<nb_edges, 256>>>(dst, E);
    assign_base_kernel<<<nb_nodes, 256>>>(N);
    place_kernel<<<nb_edges, 256>>>(src, dst, w, E);

    cudaStreamWaitEvent(0, evJoin, 0);

    int nb_agg = (N * 32 + 255) / 256;   // one warp per node
    aggregate_kernel<<<nb_agg, 256>>>(out, N);

    // Clean up only when not capturing (destroying capture-forked resources
    // would invalidate the graph). Leaked handles on capture calls are
    // bounded (harness calls kernel_launch a fixed small number of times).
    cudaStreamCaptureStatus st = cudaStreamCaptureStatusNone;
    cudaStreamIsCapturing(0, &st);
    if (st == cudaStreamCaptureStatusNone) {
        cudaStreamDestroy(s2);
        cudaEventDestroy(evFork);
        cudaEventDestroy(evJoin);
    }
}

// round 7
// speedup vs baseline: 2.6459x; 1.1436x over previous
#include <cuda_runtime.h>
#include <cuda_fp16.h>
#include <cstdint>

#define D 128
#define BM 64
#define N_MAX 100000
#define E_MAX 3200000

// ---- packed f32x2 helpers (2x fp32 FMA throughput on sm_103a) -------------
#define FMA_F32X2(d, a, b, c) \
    asm("fma.rn.f32x2 %0, %1, %2, %3;" : "=l"(d) : "l"(a), "l"(b), "l"(c))
#define ADD_F32X2(d, a, b) \
    asm("add.rn.f32x2 %0, %1, %2;" : "=l"(d) : "l"(a), "l"(b))
#define PACK_DUP_F32X2(out, r) \
    asm("mov.b64 %0, {%1, %1};" : "=l"(out) : "r"(r))

// bit-reinterpret helpers (the intrinsics I used last round don't exist)
static __device__ __forceinline__ unsigned h2_to_u32(__half2 h) {
    return *reinterpret_cast<unsigned*>(&h);
}
static __device__ __forceinline__ __half2 u32_to_h2(unsigned u) {
    return *reinterpret_cast<__half2*>(&u);
}

// Scratch
__device__ uint2  g_hh[N_MAX * 32];        // h in fp16: 4 halves per lane-slot
__device__ float4 g_wt4[D * D / 4];        // W^T
__device__ int    g_cnt[N_MAX];            // histogram -> cursor -> seg end
__device__ int    g_base[N_MAX];           // segment start per node
__device__ int    g_total;                 // bump allocator
__device__ int2   g_edge[E_MAX];           // grouped (src, w-bits) per slot

// ---------------------------------------------------------------------------
__global__ void zero_kernel(int n_nodes) {
    int i = blockIdx.x * blockDim.x + threadIdx.x;
    if (i < n_nodes) g_cnt[i] = 0;
    if (i == 0) g_total = 0;
}

__global__ void transpose_w_kernel(const float* __restrict__ W) {
    int idx = blockIdx.x * blockDim.x + threadIdx.x;
    int j = idx >> 7;
    int k = idx & (D - 1);
    ((float*)g_wt4)[k * D + j] = W[j * D + k];
}

__global__ void hist_kernel(const int* __restrict__ dst, int n_edges) {
    int e = blockIdx.x * blockDim.x + threadIdx.x;
    if (e < n_edges) atomicAdd(&g_cnt[dst[e]], 1);
}

__global__ void assign_base_kernel(int n_nodes) {
    __shared__ int warp_tot[8];
    __shared__ int block_base;
    int i = blockIdx.x * 256 + threadIdx.x;
    int lane = threadIdx.x & 31;
    int warp = threadIdx.x >> 5;

    int c = (i < n_nodes) ? g_cnt[i] : 0;
    int v = c;
    #pragma unroll
    for (int off = 1; off < 32; off <<= 1) {
        int t = __shfl_up_sync(0xffffffffu, v, off);
        if (lane >= off) v += t;
    }
    if (lane == 31) warp_tot[warp] = v;
    __syncthreads();
    if (warp == 0) {
        int wv = (lane < 8) ? warp_tot[lane] : 0;
        #pragma unroll
        for (int off = 1; off < 8; off <<= 1) {
            int t = __shfl_up_sync(0xffffffffu, wv, off);
            if (lane >= off) wv += t;
        }
        if (lane < 8) warp_tot[lane] = wv;
        if (lane == 7) block_base = atomicAdd(&g_total, wv);
    }
    __syncthreads();
    int excl = v - c + (warp > 0 ? warp_tot[warp - 1] : 0);
    if (i < n_nodes) {
        int base = block_base + excl;
        g_base[i] = base;
        g_cnt[i]  = base;
    }
}

__global__ void place_kernel(const int* __restrict__ src,
                             const int* __restrict__ dst,
                             const float* __restrict__ w,
                             int n_edges) {
    int e = blockIdx.x * blockDim.x + threadIdx.x;
    if (e >= n_edges) return;
    int d = dst[e];
    int pos = atomicAdd(&g_cnt[d], 1);
    g_edge[pos] = make_int2(src[e], __float_as_int(w[e]));
}

// ---------------------------------------------------------------------------
// GEMM: h = x @ W^T + b with packed f32x2 FMA; epilogue rounds h to fp16.
// ---------------------------------------------------------------------------
__global__ __launch_bounds__(256, 2)
void gemm_kernel(const float* __restrict__ x, const float* __restrict__ bias,
                 int n_rows) {
    extern __shared__ float4 smem4[];
    float4* Ws4 = smem4;                 // [128][32] f4: row k holds W^T[k][:]
    float4* Xs4 = smem4 + D * (D / 4);   // [64][32]  f4

    const int tid  = threadIdx.x;
    const int row0 = blockIdx.x * BM;
    const int rows = min(BM, n_rows - row0);

    #pragma unroll
    for (int i = 0; i < (D * D / 4) / 256; i++)
        Ws4[tid + i * 256] = g_wt4[tid + i * 256];
    {
        const float4* x4 = (const float4*)(x + (long long)row0 * D);
        const int nf4 = rows * (D / 4);
        for (int i = tid; i < nf4; i += 256)
            Xs4[i] = x4[i];
    }
    __syncthreads();

    const int warp = tid >> 5;
    const int lane = tid & 31;
    const int r0 = warp * 8;

    const ulonglong2* Ws2 = (const ulonglong2*)Ws4;

    unsigned long long acc[8][2];
    #pragma unroll
    for (int i = 0; i < 8; i++) { acc[i][0] = 0ull; acc[i][1] = 0ull; }

    #pragma unroll 4
    for (int k = 0; k < D; k += 4) {
        ulonglong2 wv0 = Ws2[(k + 0) * 32 + lane];
        ulonglong2 wv1 = Ws2[(k + 1) * 32 + lane];
        ulonglong2 wv2 = Ws2[(k + 2) * 32 + lane];
        ulonglong2 wv3 = Ws2[(k + 3) * 32 + lane];
        #pragma unroll
        for (int i = 0; i < 8; i++) {
            float4 xv = Xs4[(r0 + i) * 32 + (k >> 2)];  // warp broadcast
            unsigned long long xd;
            PACK_DUP_F32X2(xd, __float_as_uint(xv.x));
            FMA_F32X2(acc[i][0], xd, wv0.x, acc[i][0]);
            FMA_F32X2(acc[i][1], xd, wv0.y, acc[i][1]);
            PACK_DUP_F32X2(xd, __float_as_uint(xv.y));
            FMA_F32X2(acc[i][0], xd, wv1.x, acc[i][0]);
            FMA_F32X2(acc[i][1], xd, wv1.y, acc[i][1]);
            PACK_DUP_F32X2(xd, __float_as_uint(xv.z));
            FMA_F32X2(acc[i][0], xd, wv2.x, acc[i][0]);
            FMA_F32X2(acc[i][1], xd, wv2.y, acc[i][1]);
            PACK_DUP_F32X2(xd, __float_as_uint(xv.w));
            FMA_F32X2(acc[i][0], xd, wv3.x, acc[i][0]);
            FMA_F32X2(acc[i][1], xd, wv3.y, acc[i][1]);
        }
    }

    // bias add (packed), round to fp16, store 8B per lane
    ulonglong2 bv = ((const ulonglong2*)bias)[lane];
    #pragma unroll
    for (int i = 0; i < 8; i++) {
        int r = r0 + i;
        if (r < rows) {
            ulonglong2 o;
            ADD_F32X2(o.x, acc[i][0], bv.x);
            ADD_F32X2(o.y, acc[i][1], bv.y);
            float2 p0 = *(float2*)&o.x;
            float2 p1 = *(float2*)&o.y;
            uint2 hh;
            hh.x = h2_to_u32(__floats2half2_rn(p0.x, p0.y));
            hh.y = h2_to_u32(__floats2half2_rn(p1.x, p1.y));
            g_hh[(long long)(row0 + r) * 32 + lane] = hh;
        }
    }
}

// ---------------------------------------------------------------------------
// aggregate: one warp per node, lane owns 4 columns. fp16 gather (8B/lane),
// fp32 accumulation; single 512B fp32 store per node. No atomics.
// ---------------------------------------------------------------------------
__global__ __launch_bounds__(256)
void aggregate_kernel(float* __restrict__ out, int n_nodes) {
    int node = (blockIdx.x * 256 + threadIdx.x) >> 5;
    int lane = threadIdx.x & 31;
    if (node >= n_nodes) return;

    int beg = g_base[node];
    int end = g_cnt[node];

    float4 acc = make_float4(0.f, 0.f, 0.f, 0.f);

    int i = beg;
    for (; i + 4 <= end; i += 4) {
        int2 e0 = g_edge[i],     e1 = g_edge[i + 1];
        int2 e2 = g_edge[i + 2], e3 = g_edge[i + 3];
        uint2 h0 = g_hh[(long long)e0.x * 32 + lane];
        uint2 h1 = g_hh[(long long)e1.x * 32 + lane];
        uint2 h2 = g_hh[(long long)e2.x * 32 + lane];
        uint2 h3 = g_hh[(long long)e3.x * 32 + lane];
        float w0 = __int_as_float(e0.y), w1 = __int_as_float(e1.y);
        float w2 = __int_as_float(e2.y), w3 = __int_as_float(e3.y);
        float2 a, bq;
        a = __half22float2(u32_to_h2(h0.x)); bq = __half22float2(u32_to_h2(h0.y));
        acc.x += a.x * w0; acc.y += a.y * w0; acc.z += bq.x * w0; acc.w += bq.y * w0;
        a = __half22float2(u32_to_h2(h1.x)); bq = __half22float2(u32_to_h2(h1.y));
        acc.x += a.x * w1; acc.y += a.y * w1; acc.z += bq.x * w1; acc.w += bq.y * w1;
        a = __half22float2(u32_to_h2(h2.x)); bq = __half22float2(u32_to_h2(h2.y));
        acc.x += a.x * w2; acc.y += a.y * w2; acc.z += bq.x * w2; acc.w += bq.y * w2;
        a = __half22float2(u32_to_h2(h3.x)); bq = __half22float2(u32_to_h2(h3.y));
        acc.x += a.x * w3; acc.y += a.y * w3; acc.z += bq.x * w3; acc.w += bq.y * w3;
    }
    for (; i < end; i++) {
        int2 e = g_edge[i];
        float wv = __int_as_float(e.y);
        uint2 hv = g_hh[(long long)e.x * 32 + lane];
        float2 a = __half22float2(u32_to_h2(hv.x));
        float2 bq = __half22float2(u32_to_h2(hv.y));
        acc.x += a.x * wv; acc.y += a.y * wv; acc.z += bq.x * wv; acc.w += bq.y * wv;
    }

    ((float4*)out)[(long long)node * 32 + lane] = acc;
}

// ---------------------------------------------------------------------------
extern "C" void kernel_launch(void* const* d_in, const int* in_sizes, int n_in,
                              void* d_out, int out_size) {
    const float* x   = (const float*)d_in[0];
    const float* w   = (const float*)d_in[1];
    const float* W   = (const float*)d_in[2];
    const float* b   = (const float*)d_in[3];
    const int*   src = (const int*)d_in[4];   // int32 (JAX x64 disabled)
    const int*   dst = (const int*)d_in[5];

    int N = in_sizes[0] / D;
    int E = in_sizes[1];
    float* out = (float*)d_out;

    int nb_nodes = (N + 255) / 256;
    int nb_edges = (E + 255) / 256;

    // Fork: GEMM (x,W,b) concurrent with edge-sort pipeline (src,dst,w).
    cudaStream_t s2;
    cudaStreamCreate(&s2);
    cudaEvent_t evFork, evJoin;
    cudaEventCreateWithFlags(&evFork, cudaEventDisableTiming);
    cudaEventCreateWithFlags(&evJoin, cudaEventDisableTiming);

    zero_kernel<<<nb_nodes, 256>>>(N);
    transpose_w_kernel<<<(D * D) / 256, 256>>>(W);

    cudaEventRecord(evFork, 0);
    cudaStreamWaitEvent(s2, evFork, 0);

    const int smem_bytes = (D * D + BM * D) * sizeof(float);  // 96 KB
    cudaFuncSetAttribute(gemm_kernel,
                         cudaFuncAttributeMaxDynamicSharedMemorySize, smem_bytes);
    gemm_kernel<<<(N + BM - 1) / BM, 256, smem_bytes, s2>>>(x, b, N);
    cudaEventRecord(evJoin, s2);

    hist_kernel<<<nb_edges, 256>>>(dst, E);
    assign_base_kernel<<<nb_nodes, 256>>>(N);
    place_kernel<<<nb_edges, 256>>>(src, dst, w, E);

    cudaStreamWaitEvent(0, evJoin, 0);

    int nb_agg = (N * 32 + 255) / 256;   // one warp per node
    aggregate_kernel<<<nb_agg, 256>>>(out, N);

    cudaStreamCaptureStatus st = cudaStreamCaptureStatusNone;
    cudaStreamIsCapturing(0, &st);
    if (st == cudaStreamCaptureStatusNone) {
        cudaStreamDestroy(s2);
        cudaEventDestroy(evFork);
        cudaEventDestroy(evJoin);
    }
}